// round 9
// baseline (speedup 1.0000x reference)
#include <cuda_runtime.h>

#define BATCH   8
#define NPTS    4096
#define THREADS 128
#define PTS     8                        // query points per thread (4 packed pairs)
#define NPAIR   (PTS / 2)
#define PTS_BLK (THREADS * PTS)          // 1024
#define XT      (NPTS / PTS_BLK)         // 4 query tiles
#define NC      64                       // reference chunks (CTAs per tile)
#define CH      (NPTS / NC)              // 64 reference pts per chunk
#define NTILES  (2 * BATCH * XT)         // 64

// Scratch (allocation-free contract). All zero-init; every replay resets what
// it consumed, so the graph is replay-deterministic.
__device__ unsigned           g_key[2 * BATCH * NPTS];  // encoded per-point mins
__device__ int                g_tctr[NTILES];           // per-tile CTA counters
__device__ unsigned long long g_total = 0ull;           // fixed-point 2^32 sum
__device__ int                g_done  = 0;              // finished-tile counter

// ---- packed f32x2 helpers -------------------------------------------------
__device__ __forceinline__ unsigned long long fma2(unsigned long long a,
                                                   unsigned long long b,
                                                   unsigned long long c) {
    unsigned long long d;
    asm("fma.rn.f32x2 %0, %1, %2, %3;" : "=l"(d) : "l"(a), "l"(b), "l"(c));
    return d;
}
__device__ __forceinline__ unsigned long long pack2(float lo, float hi) {
    unsigned long long v;
    asm("mov.b64 %0, {%1, %2};" : "=l"(v) : "f"(lo), "f"(hi));
    return v;
}
__device__ __forceinline__ float2 unpack2(unsigned long long v) {
    float2 r;
    asm("mov.b64 {%0, %1}, %2;" : "=f"(r.x), "=f"(r.y) : "l"(v));
    return r;
}

// Order-preserving float -> uint map, inverted so min(f) == max(key) and
// key 0 means "empty" (no finite float maps to 0).
__device__ __forceinline__ unsigned min_key(float f) {
    unsigned u = __float_as_uint(f);
    u ^= (unsigned)(((int)u >> 31)) | 0x80000000u;
    return ~u;
}
__device__ __forceinline__ float key_to_float(unsigned key) {
    unsigned mono = ~key;
    unsigned bits = (mono & 0x80000000u) ? (mono ^ 0x80000000u) : ~mono;
    return __uint_as_float(bits);
}

// ---- single fused kernel --------------------------------------------------
// Per (dir, b, query-tile, ref-chunk) CTA: min over chunk of (qq - 2*p.q),
// folded via atomicMax on encoded keys. Last CTA of each tile consumes the
// tile's keys (its own points), adds back |p|^2, and folds a fixed-point
// partial into g_total; the globally-last tile writes the scalar mean.
__global__ void __launch_bounds__(THREADS)
chamfer_main(const float* __restrict__ X, const float* __restrict__ Y,
             float* __restrict__ out) {
    // Pre-duplicated reference layout, 32 B/point (+1 pad point for prefetch):
    //   float4 #0 = (q0,q0, q1,q1), float4 #1 = (q2,q2, qq,qq)
    __shared__ float4 sq[CH * 2 + 2];

    int bid = blockIdx.x;
    int c   = bid & (NC - 1);   bid >>= 6;
    int xt  = bid & (XT - 1);   bid >>= 2;
    int b   = bid & (BATCH-1);  bid >>= 3;
    int dir = bid;                        // 0: x->y, 1: y->x

    const float* P  = dir ? Y : X;        // query set
    const float* Q  = dir ? X : Y;        // reference set
    const float* Qb = Q + b * 3 * NPTS;
    const float* Pb = P + b * 3 * NPTS;

    int tid = threadIdx.x;

    // Stage reference chunk (duplicated lanes for f32x2 broadcast).
    if (tid < CH) {
        int gm   = c * CH + tid;
        float q0 = Qb[gm];
        float q1 = Qb[gm + NPTS];
        float q2 = Qb[gm + 2 * NPTS];
        float qq = q0*q0 + q1*q1 + q2*q2;
        sq[tid * 2 + 0] = make_float4(q0, q0, q1, q1);
        sq[tid * 2 + 1] = make_float4(q2, q2, qq, qq);
    }
    __syncthreads();

    // 4 packed query pairs per thread, coefficients pre-scaled by -2.
    unsigned long long pa0[NPAIR], pa1[NPAIR], pa2[NPAIR];
    float mn[PTS];
    #pragma unroll
    for (int p = 0; p < NPAIR; p++) {
        int n0 = xt * PTS_BLK + (2*p)   * THREADS + tid;
        int n1 = xt * PTS_BLK + (2*p+1) * THREADS + tid;
        pa0[p] = pack2(-2.0f * Pb[n0],            -2.0f * Pb[n1]);
        pa1[p] = pack2(-2.0f * Pb[n0 + NPTS],     -2.0f * Pb[n1 + NPTS]);
        pa2[p] = pack2(-2.0f * Pb[n0 + 2*NPTS],   -2.0f * Pb[n1 + 2*NPTS]);
        mn[2*p] = 3.0e38f; mn[2*p+1] = 3.0e38f;
    }

    // Inner loop with one-iteration register prefetch to hide LDS latency.
    const ulonglong2* s2 = reinterpret_cast<const ulonglong2*>(sq);
    ulonglong2 A = s2[0];                 // A.x={q0,q0}  A.y={q1,q1}
    ulonglong2 B = s2[1];                 // B.x={q2,q2}  B.y={qq,qq}
    #pragma unroll 2
    for (int j = 0; j < CH; j++) {
        ulonglong2 An = s2[2*j + 2];
        ulonglong2 Bn = s2[2*j + 3];
        #pragma unroll
        for (int p = 0; p < NPAIR; p++) {
            unsigned long long t =
                fma2(pa0[p], A.x, fma2(pa1[p], A.y, fma2(pa2[p], B.x, B.y)));
            float2 tf = unpack2(t);
            mn[2*p]   = fminf(mn[2*p],   tf.x);
            mn[2*p+1] = fminf(mn[2*p+1], tf.y);
        }
        A = An; B = Bn;
    }

    // Fold chunk mins into the global per-point min (fire-and-forget REDG.MAX).
    int tile = (dir * BATCH + b) * XT + xt;
    unsigned* gk = g_key + (dir * BATCH + b) * NPTS + xt * PTS_BLK;
    #pragma unroll
    for (int k = 0; k < PTS; k++)
        atomicMax(&gk[k * THREADS + tid], min_key(mn[k]));

    // ---- tile-last epilogue ----
    __threadfence();
    __shared__ bool last_tile;
    __shared__ float red[THREADS];
    if (tid == 0) {
        int prev = atomicAdd(&g_tctr[tile], 1);
        last_tile = (prev == NC - 1);
    }
    __syncthreads();
    if (!last_tile) return;

    if (tid == 0) g_tctr[tile] = 0;       // reset for next replay

    // This CTA's PTS points are exactly the tile's 1024 points.
    float s = 0.0f;
    #pragma unroll
    for (int p = 0; p < NPAIR; p++) {
        float2 u0 = unpack2(pa0[p]), u1 = unpack2(pa1[p]), u2 = unpack2(pa2[p]);
        float pplo = 0.25f * (u0.x*u0.x + u1.x*u1.x + u2.x*u2.x);
        float pphi = 0.25f * (u0.y*u0.y + u1.y*u1.y + u2.y*u2.y);
        int i0 = (2*p)   * THREADS + tid;
        int i1 = (2*p+1) * THREADS + tid;
        unsigned k0 = *((volatile unsigned*)&gk[i0]);
        unsigned k1 = *((volatile unsigned*)&gk[i1]);
        gk[i0] = 0u;  gk[i1] = 0u;        // reset for next replay
        s += key_to_float(k0) + pplo;
        s += key_to_float(k1) + pphi;
    }

    red[tid] = s;
    __syncthreads();
    #pragma unroll
    for (int st = THREADS / 2; st > 0; st >>= 1) {
        if (tid < st) red[tid] += red[tid + st];
        __syncthreads();
    }

    if (tid == 0) {
        // Deterministic global fold: fixed-point (2^32) u64 accumulation.
        unsigned long long fx =
            (unsigned long long)((double)red[0] * 4294967296.0);
        atomicAdd(&g_total, fx);
        __threadfence();
        int prev = atomicAdd(&g_done, 1);
        if (prev == NTILES - 1) {
            unsigned long long tot = atomicAdd(&g_total, 0ull);
            out[0] = (float)((double)tot * (1.0 / 4294967296.0)
                             / (double)(NPTS * BATCH));
            g_total = 0ull;               // reset for next replay
            g_done  = 0;
        }
    }
}

extern "C" void kernel_launch(void* const* d_in, const int* in_sizes, int n_in,
                              void* d_out, int out_size) {
    const float* x = (const float*)d_in[0];
    const float* y = (const float*)d_in[1];
    float* out = (float*)d_out;

    chamfer_main<<<2 * BATCH * XT * NC, THREADS>>>(x, y, out);
}

// round 13
// speedup vs baseline: 1.3085x; 1.3085x over previous
#include <cuda_runtime.h>

#define BATCH   8
#define NPTS    4096
#define THREADS 128
#define PTS     8                        // x points per thread (4 packed pairs)
#define NPAIR   (PTS / 2)
#define PTS_BLK (THREADS * PTS)          // 1024 x-points per tile
#define XT      (NPTS / PTS_BLK)         // 4 x tiles
#define NC      64                       // y chunks
#define CH      (NPTS / NC)              // 64 y-points per chunk
#define NCTAS   (BATCH * XT * NC)        // 2048
#define CPITCH  65                       // smem col pitch (bank-conflict-free)

// Scratch (allocation-free contract). Zero-init == "empty" keys; each replay
// resets everything it consumed -> graph-replay deterministic.
__device__ unsigned           g_xkey[BATCH * NPTS];
__device__ unsigned           g_ykey[BATCH * NPTS];
__device__ int                g_xctr[BATCH * XT];
__device__ int                g_yctr[BATCH * NC];
__device__ unsigned long long g_total = 0ull;
__device__ int                g_done  = 0;

// ---- packed f32x2 helpers -------------------------------------------------
__device__ __forceinline__ unsigned long long fma2(unsigned long long a,
                                                   unsigned long long b,
                                                   unsigned long long c) {
    unsigned long long d;
    asm("fma.rn.f32x2 %0, %1, %2, %3;" : "=l"(d) : "l"(a), "l"(b), "l"(c));
    return d;
}
__device__ __forceinline__ unsigned long long add2(unsigned long long a,
                                                   unsigned long long b) {
    unsigned long long d;
    asm("add.rn.f32x2 %0, %1, %2;" : "=l"(d) : "l"(a), "l"(b));
    return d;
}
__device__ __forceinline__ unsigned long long pack2(float lo, float hi) {
    unsigned long long v;
    asm("mov.b64 %0, {%1, %2};" : "=l"(v) : "f"(lo), "f"(hi));
    return v;
}
__device__ __forceinline__ float2 unpack2(unsigned long long v) {
    float2 r;
    asm("mov.b64 {%0, %1}, %2;" : "=f"(r.x), "=f"(r.y) : "l"(v));
    return r;
}

// Order-preserving float -> uint map, inverted: min(f) == max(key), key 0 = empty.
__device__ __forceinline__ unsigned min_key(float f) {
    unsigned u = __float_as_uint(f);
    u ^= (unsigned)(((int)u >> 31)) | 0x80000000u;
    return ~u;
}
__device__ __forceinline__ float key_to_float(unsigned key) {
    unsigned mono = ~key;
    unsigned bits = (mono & 0x80000000u) ? (mono ^ 0x80000000u) : ~mono;
    return __uint_as_float(bits);
}

// Ordering rides on atomics (no membar -> no CCTL.IVALL L1 flush).
__device__ __forceinline__ int atom_add_acq_rel(int* p, int v) {
    int old;
    asm volatile("atom.acq_rel.gpu.global.add.s32 %0, [%1], %2;"
                 : "=r"(old) : "l"(p), "r"(v) : "memory");
    return old;
}
__device__ __forceinline__ void red_add_release(unsigned long long* p,
                                                unsigned long long v) {
    asm volatile("red.release.gpu.global.add.u64 [%0], %1;"
                 :: "l"(p), "l"(v) : "memory");
}

// ---- single symmetric fused kernel ----------------------------------------
// Each CTA: one (b, x-tile[1024], y-chunk[64]) tile. Distances computed ONCE,
// folded into BOTH x-side row mins and y-side column mins via atomicMax keys.
__global__ void __launch_bounds__(THREADS, 6)
chamfer_fused(const float* __restrict__ X, const float* __restrict__ Y,
              float* __restrict__ out) {
    __shared__ float4 sq[CH * 2 + 2];       // (q,q,q1,q1 | q2,q2,qq,qq) + pad
    __shared__ float  scol[THREADS * CPITCH];
    __shared__ float  red[THREADS];
    __shared__ int    sflags;

    int bid = blockIdx.x;
    int c   = bid & (NC - 1);  bid >>= 6;
    int xt  = bid & (XT - 1);  bid >>= 2;
    int b   = bid;

    const float* Xb = X + b * 3 * NPTS;
    const float* Yb = Y + b * 3 * NPTS;
    int tid = threadIdx.x;

    // Stage y chunk (duplicated lanes for f32x2 broadcast). CH <= THREADS.
    if (tid < CH) {
        int gm   = c * CH + tid;
        float q0 = Yb[gm];
        float q1 = Yb[gm + NPTS];
        float q2 = Yb[gm + 2 * NPTS];
        float qq = q0*q0 + q1*q1 + q2*q2;
        sq[tid * 2 + 0] = make_float4(q0, q0, q1, q1);
        sq[tid * 2 + 1] = make_float4(q2, q2, qq, qq);
    }
    __syncthreads();

    // 4 packed x pairs per thread: coeffs -2x, plus packed |x|^2.
    unsigned long long pa0[NPAIR], pa1[NPAIR], pa2[NPAIR], pp[NPAIR];
    float mn[PTS];
    #pragma unroll
    for (int p = 0; p < NPAIR; p++) {
        int n0 = xt * PTS_BLK + (2*p)   * THREADS + tid;
        int n1 = xt * PTS_BLK + (2*p+1) * THREADS + tid;
        float x0l = Xb[n0],          x0h = Xb[n1];
        float x1l = Xb[n0 + NPTS],   x1h = Xb[n1 + NPTS];
        float x2l = Xb[n0 + 2*NPTS], x2h = Xb[n1 + 2*NPTS];
        pa0[p] = pack2(-2.0f * x0l, -2.0f * x0h);
        pa1[p] = pack2(-2.0f * x1l, -2.0f * x1h);
        pa2[p] = pack2(-2.0f * x2l, -2.0f * x2h);
        pp[p]  = pack2(x0l*x0l + x1l*x1l + x2l*x2l,
                       x0h*x0h + x1h*x1h + x2h*x2h);
        mn[2*p] = 3.0e38f; mn[2*p+1] = 3.0e38f;
    }

    // Inner loop: t = qq - 2 x.q  (row mins use t; col mins use t + pp = d).
    const ulonglong2* s2 = reinterpret_cast<const ulonglong2*>(sq);
    ulonglong2 A = s2[0];
    ulonglong2 B = s2[1];
    #pragma unroll 2
    for (int j = 0; j < CH; j++) {
        ulonglong2 An = s2[2*j + 2];
        ulonglong2 Bn = s2[2*j + 3];
        float cv[NPAIR];
        #pragma unroll
        for (int p = 0; p < NPAIR; p++) {
            unsigned long long t =
                fma2(pa0[p], A.x, fma2(pa1[p], A.y, fma2(pa2[p], B.x, B.y)));
            float2 tf = unpack2(t);
            mn[2*p]   = fminf(mn[2*p],   tf.x);
            mn[2*p+1] = fminf(mn[2*p+1], tf.y);
            float2 cf = unpack2(add2(t, pp[p]));
            cv[p] = fminf(cf.x, cf.y);
        }
        scol[tid * CPITCH + j] =
            fminf(fminf(cv[0], cv[1]), fminf(cv[2], cv[3]));
        A = An; B = Bn;
    }

    // Fold x-side row mins (fire-and-forget REDG.MAX).
    unsigned* gx = g_xkey + b * NPTS + xt * PTS_BLK;
    #pragma unroll
    for (int k = 0; k < PTS; k++)
        atomicMax(&gx[k * THREADS + tid], min_key(mn[k]));

    __syncthreads();

    // Cross-thread column mins, fold y-side.
    if (tid < CH) {
        float v = 3.0e38f;
        #pragma unroll 8
        for (int t2 = 0; t2 < THREADS; t2++)
            v = fminf(v, scol[t2 * CPITCH + tid]);
        atomicMax(&g_ykey[b * NPTS + c * CH + tid], min_key(v));
    }

    // ---- tile-last epilogues (ordering via acq_rel atomics, no membar) ----
    if (tid == 0) {
        int f = 0;
        if (atom_add_acq_rel(&g_xctr[b * XT + xt], 1) == NC - 1) f |= 1;
        if (atom_add_acq_rel(&g_yctr[b * NC + c], 1) == XT - 1) f |= 2;
        sflags = f;
    }
    __syncthreads();
    int f = sflags;

    if (f) {
        float part = 0.0f;
        if (f & 1) {                       // x-tile complete: its 1024 points
            if (tid == 0) g_xctr[b * XT + xt] = 0;
            #pragma unroll
            for (int p = 0; p < NPAIR; p++) {
                float2 pf = unpack2(pp[p]);
                int i0 = (2*p)   * THREADS + tid;
                int i1 = (2*p+1) * THREADS + tid;
                unsigned k0 = *((volatile unsigned*)&gx[i0]);
                unsigned k1 = *((volatile unsigned*)&gx[i1]);
                gx[i0] = 0u; gx[i1] = 0u;  // reset for next replay
                part += key_to_float(k0) + pf.x;
                part += key_to_float(k1) + pf.y;
            }
        }
        if (f & 2) {                       // y-chunk complete: 64 full dists
            if (tid == 0) g_yctr[b * NC + c] = 0;
            if (tid < CH) {
                unsigned* gy = g_ykey + b * NPTS + c * CH + tid;
                unsigned k = *((volatile unsigned*)gy);
                *gy = 0u;                  // reset for next replay
                part += key_to_float(k);
            }
        }
        red[tid] = part;
        __syncthreads();
        #pragma unroll
        for (int st = THREADS / 2; st > 0; st >>= 1) {
            if (tid < st) red[tid] += red[tid + st];
            __syncthreads();
        }
        if (tid == 0)                      // deterministic fixed-point fold
            red_add_release(&g_total,
                (unsigned long long)((double)red[0] * 4294967296.0));
    }

    if (tid == 0) {
        if (atom_add_acq_rel(&g_done, 1) == NCTAS - 1) {
            unsigned long long tot = *((volatile unsigned long long*)&g_total);
            out[0] = (float)((double)tot * (1.0 / 4294967296.0)
                             / (double)(NPTS * BATCH));
            g_total = 0ull;                // reset for next replay
            g_done  = 0;
        }
    }
}

extern "C" void kernel_launch(void* const* d_in, const int* in_sizes, int n_in,
                              void* d_out, int out_size) {
    const float* x = (const float*)d_in[0];
    const float* y = (const float*)d_in[1];
    float* out = (float*)d_out;

    chamfer_fused<<<NCTAS, THREADS>>>(x, y, out);
}